// round 7
// baseline (speedup 1.0000x reference)
#include <cuda_runtime.h>

#define NN 100000
#define EE 800000
#define DD 64

// Scratch (allocation-free rule: __device__ globals)
__device__ float g_xt[NN * DD];     // xt = dis_v * (sum dis_u*x_u + dis_v*x_v)
__device__ float g_x[NN * DD];      // ping-pong x between rounds
__device__ int   g_deg[NN];
__device__ int   g_rowptr[NN + 1];
__device__ int   g_cursor[NN];
__device__ int   g_col[EE];
__device__ float g_dis[NN];

// ---------------- CSR build ----------------

__global__ void k_hist(const int* __restrict__ dst, int e) {
    int i = blockIdx.x * blockDim.x + threadIdx.x;
    if (i < e) atomicAdd(&g_deg[dst[i]], 1);
}

// Single-block exclusive scan; dis = rsqrt(deg+1); re-zeroes g_deg for the
// next launch (initial state is zero from static init -> replay-identical).
__global__ void k_scan(int n) {
    __shared__ int part[1024];
    int t = threadIdx.x;
    int C = (n + 1023) / 1024;
    int lo = t * C;
    int hi = min(lo + C, n);
    int s = 0;
    for (int i = lo; i < hi; i++) s += g_deg[i];
    part[t] = s;
    __syncthreads();
    for (int off = 1; off < 1024; off <<= 1) {
        int v = (t >= off) ? part[t - off] : 0;
        __syncthreads();
        part[t] += v;
        __syncthreads();
    }
    int run = (t == 0) ? 0 : part[t - 1];
    for (int i = lo; i < hi; i++) {
        int d = g_deg[i];
        g_deg[i] = 0;
        g_rowptr[i] = run;
        g_cursor[i] = run;
        g_dis[i] = rsqrtf((float)(d + 1));   // +1 self-loop
        run += d;
    }
    if (t == 1023) g_rowptr[n] = run;
}

__global__ void k_scatter(const int* __restrict__ src, const int* __restrict__ dst, int e) {
    int i = blockIdx.x * blockDim.x + threadIdx.x;
    if (i < e) {
        int d = dst[i];
        int pos = atomicAdd(&g_cursor[d], 1);
        g_col[pos] = src[i];
    }
}

// ---------------- per-round kernels ----------------

// One warp per node v (round-2 measured kernel, 138.8us):
//   xt[v] = dis_v * ( sum_{u->v} dis_u * x[u]  +  dis_v * x[v] )
__global__ __launch_bounds__(256) void k_agg(const float* __restrict__ xin,
                                             float* __restrict__ xt, int n) {
    int wid  = (blockIdx.x * blockDim.x + threadIdx.x) >> 5;
    int lane = threadIdx.x & 31;
    if (wid >= n) return;
    int v = wid;

    const float2* x2 = (const float2*)xin;
    float dv = g_dis[v];
    float2 self = x2[(size_t)v * 32 + lane];
    float2 acc;
    acc.x = dv * self.x;
    acc.y = dv * self.y;

    int rp0 = g_rowptr[v];
    int rp1 = g_rowptr[v + 1];
    for (int base = rp0; base < rp1; base += 32) {
        int j = base + lane;
        int c = 0;
        float du = 0.f;
        if (j < rp1) { c = g_col[j]; du = g_dis[c]; }
        int cnt = min(32, rp1 - base);
        int jj = 0;
        for (; jj + 4 <= cnt; jj += 4) {
            int u0 = __shfl_sync(0xffffffffu, c, jj + 0);
            int u1 = __shfl_sync(0xffffffffu, c, jj + 1);
            int u2 = __shfl_sync(0xffffffffu, c, jj + 2);
            int u3 = __shfl_sync(0xffffffffu, c, jj + 3);
            float d0 = __shfl_sync(0xffffffffu, du, jj + 0);
            float d1 = __shfl_sync(0xffffffffu, du, jj + 1);
            float d2 = __shfl_sync(0xffffffffu, du, jj + 2);
            float d3 = __shfl_sync(0xffffffffu, du, jj + 3);
            float2 m0 = x2[(size_t)u0 * 32 + lane];
            float2 m1 = x2[(size_t)u1 * 32 + lane];
            float2 m2 = x2[(size_t)u2 * 32 + lane];
            float2 m3 = x2[(size_t)u3 * 32 + lane];
            acc.x += d0 * m0.x; acc.y += d0 * m0.y;
            acc.x += d1 * m1.x; acc.y += d1 * m1.y;
            acc.x += d2 * m2.x; acc.y += d2 * m2.y;
            acc.x += d3 * m3.x; acc.y += d3 * m3.y;
        }
        for (; jj < cnt; jj++) {
            int   u = __shfl_sync(0xffffffffu, c, jj);
            float d = __shfl_sync(0xffffffffu, du, jj);
            float2 m = x2[(size_t)u * 32 + lane];
            acc.x += d * m.x;
            acc.y += d * m.y;
        }
    }

    acc.x *= dv;
    acc.y *= dv;
    ((float2*)xt)[(size_t)v * 32 + lane] = acc;
}

// out = LayerNorm( xt @ W + b ) * gamma + beta
// 4x4-register GEMM (proven ~FFMA floor), then acc staged to smem and a
// warp-per-row LN epilogue (the proven 2-value/lane reduction). Low regs.
__global__ __launch_bounds__(256) void k_gemm_ln(const float* __restrict__ xt,
                                                 const float* __restrict__ W,
                                                 const float* __restrict__ b,
                                                 const float* __restrict__ gamma,
                                                 const float* __restrict__ beta,
                                                 float* __restrict__ out, int n) {
    __shared__ float Wsh[DD * DD];      // [k][c]
    __shared__ float Xsh[DD * DD];      // [r][k] -> reused as output tile [r][c]

    int t = threadIdx.x;
    int rowbase = blockIdx.x * 64;

    {
        const float4* W4 = (const float4*)W;
        float4* Ws4 = (float4*)Wsh;
        #pragma unroll
        for (int i = t; i < 1024; i += 256) Ws4[i] = W4[i];
    }
    {
        float4* Xs4 = (float4*)Xsh;
        #pragma unroll
        for (int i = t; i < 1024; i += 256) {
            int r = i >> 4, k4 = i & 15;
            float4 v = make_float4(0.f, 0.f, 0.f, 0.f);
            if (rowbase + r < n)
                v = ((const float4*)(xt + (size_t)(rowbase + r) * DD))[k4];
            Xs4[i] = v;
        }
    }
    __syncthreads();

    int tx = t & 15;        // cols tx*4 .. tx*4+3
    int ty = t >> 4;        // rows ty*4 .. ty*4+3

    float acc[4][4];
    #pragma unroll
    for (int i = 0; i < 4; i++)
        #pragma unroll
        for (int j = 0; j < 4; j++) acc[i][j] = 0.f;

    #pragma unroll 8
    for (int k = 0; k < 64; k++) {
        float4 w = ((const float4*)(Wsh + k * DD))[tx];
        float a0 = Xsh[(ty * 4 + 0) * DD + k];
        float a1 = Xsh[(ty * 4 + 1) * DD + k];
        float a2 = Xsh[(ty * 4 + 2) * DD + k];
        float a3 = Xsh[(ty * 4 + 3) * DD + k];
        acc[0][0] += a0 * w.x; acc[0][1] += a0 * w.y; acc[0][2] += a0 * w.z; acc[0][3] += a0 * w.w;
        acc[1][0] += a1 * w.x; acc[1][1] += a1 * w.y; acc[1][2] += a1 * w.z; acc[1][3] += a1 * w.w;
        acc[2][0] += a2 * w.x; acc[2][1] += a2 * w.y; acc[2][2] += a2 * w.z; acc[2][3] += a2 * w.w;
        acc[3][0] += a3 * w.x; acc[3][1] += a3 * w.y; acc[3][2] += a3 * w.z; acc[3][3] += a3 * w.w;
    }

    // Stage acc (+bias) into Xsh as the output tile [row][col]
    __syncthreads();   // everyone done reading Xsh as input
    float4 bb = ((const float4*)b)[tx];
    #pragma unroll
    for (int i = 0; i < 4; i++) {
        float4 o = make_float4(acc[i][0] + bb.x, acc[i][1] + bb.y,
                               acc[i][2] + bb.z, acc[i][3] + bb.w);
        ((float4*)Xsh)[(ty * 4 + i) * 16 + tx] = o;
    }
    __syncthreads();

    // LN epilogue: 8 warps x 8 rows each; 2 features per lane
    int warp = t >> 5;
    int lane = t & 31;
    float2 gm = ((const float2*)gamma)[lane];
    float2 bt = ((const float2*)beta)[lane];

    #pragma unroll
    for (int rr = 0; rr < 8; rr++) {
        int row = warp * 8 + rr;
        float2 a = ((const float2*)Xsh)[row * 32 + lane];
        float s  = a.x + a.y;
        float ss = a.x * a.x + a.y * a.y;
        #pragma unroll
        for (int o = 16; o > 0; o >>= 1) {
            s  += __shfl_xor_sync(0xffffffffu, s, o);
            ss += __shfl_xor_sync(0xffffffffu, ss, o);
        }
        float mu  = s * (1.f / 64.f);
        float var = ss * (1.f / 64.f) - mu * mu;
        float inv = rsqrtf(var + 1e-5f);
        int grow = rowbase + row;
        if (grow < n) {
            float2 o2;
            o2.x = (a.x - mu) * inv * gm.x + bt.x;
            o2.y = (a.y - mu) * inv * gm.y + bt.y;
            ((float2*)out)[(size_t)grow * 32 + lane] = o2;
        }
    }
}

// ---------------- launch ----------------

extern "C" void kernel_launch(void* const* d_in, const int* in_sizes, int n_in,
                              void* d_out, int out_size) {
    const float* x     = (const float*)d_in[0];
    const int*   ei    = (const int*)d_in[1];
    const float* W     = (const float*)d_in[2];
    const float* b     = (const float*)d_in[3];
    const float* gamma = (const float*)d_in[4];
    const float* beta  = (const float*)d_in[5];

    int n = in_sizes[0] / DD;      // 100000
    int e = in_sizes[1] / 2;       // 800000
    const int* src = ei;
    const int* dst = ei + e;

    k_hist<<<(e + 255) / 256, 256>>>(dst, e);          // kernel 1
    k_scan<<<1, 1024>>>(n);                            // kernel 2
    k_scatter<<<(e + 255) / 256, 256>>>(src, dst, e);  // kernel 3

    int gemm_blocks = (n + 63) / 64;
    int agg_blocks  = (n + 7) / 8;   // warp per node, 8 warps/block

    const int NUM_ROUNDS = 4;
    for (int r = 0; r < NUM_ROUNDS; r++) {
        const float* xin = (r == 0) ? x : (const float*)g_x;
        float* xout = (r == NUM_ROUNDS - 1) ? (float*)d_out : g_x;
        k_agg<<<agg_blocks, 256>>>(xin, (float*)g_xt, n);   // kernel 4 on r=0 -> PROFILED
        k_gemm_ln<<<gemm_blocks, 256>>>((const float*)g_xt, W, b, gamma, beta, xout, n);
    }
}

// round 8
// speedup vs baseline: 3.9244x; 3.9244x over previous
#include <cuda_runtime.h>

#define NN 100000
#define EE 800000
#define DD 64

// Scratch (allocation-free rule: __device__ globals).
// g_g has ONE EXTRA ROW (index NN), never written -> stays zero from static
// init; gather target for padding lanes (branch-free 8-deep gather blocks).
__device__ float g_g[(NN + 1) * DD];
__device__ float g_x[NN * DD];      // ping-pong x between rounds
__device__ int   g_deg[NN];
__device__ int   g_rowptr[NN + 1];
__device__ int   g_cursor[NN];
__device__ int   g_col[EE];
__device__ float g_dis[NN];

// ---------------- CSR build ----------------

__global__ void k_hist(const int* __restrict__ dst, int e) {
    int i = blockIdx.x * blockDim.x + threadIdx.x;
    if (i < e) atomicAdd(&g_deg[dst[i]], 1);
}

// Single-block exclusive scan; dis = rsqrt(deg+1); re-zeroes g_deg so the
// next launch's k_hist starts from zero (static init -> replay-identical).
__global__ void k_scan(int n) {
    __shared__ int part[1024];
    int t = threadIdx.x;
    int C = (n + 1023) / 1024;
    int lo = t * C;
    int hi = min(lo + C, n);
    int s = 0;
    for (int i = lo; i < hi; i++) s += g_deg[i];
    part[t] = s;
    __syncthreads();
    for (int off = 1; off < 1024; off <<= 1) {
        int v = (t >= off) ? part[t - off] : 0;
        __syncthreads();
        part[t] += v;
        __syncthreads();
    }
    int run = (t == 0) ? 0 : part[t - 1];
    for (int i = lo; i < hi; i++) {
        int d = g_deg[i];
        g_deg[i] = 0;
        g_rowptr[i] = run;
        g_cursor[i] = run;
        g_dis[i] = rsqrtf((float)(d + 1));   // +1 self-loop
        run += d;
    }
    if (t == 1023) g_rowptr[n] = run;
}

__global__ void k_scatter(const int* __restrict__ src, const int* __restrict__ dst, int e) {
    int i = blockIdx.x * blockDim.x + threadIdx.x;
    if (i < e) {
        int d = dst[i];
        int pos = atomicAdd(&g_cursor[d], 1);
        g_col[pos] = src[i];
    }
}

// ---------------- per-round kernels ----------------

// g = dis[r] * (x @ W). 64x64 tile per block, 256 threads, 4x4 outputs each.
// (~FFMA floor, 26.5us measured; writes only rows < n, pad row NN stays zero.)
__global__ __launch_bounds__(256) void k_gemm(const float* __restrict__ x,
                                              const float* __restrict__ W, int n) {
    __shared__ float Wsh[DD * DD];
    __shared__ float Xsh[DD * DD];

    int t = threadIdx.x;
    int rowbase = blockIdx.x * 64;

    {
        const float4* W4 = (const float4*)W;
        float4* Ws4 = (float4*)Wsh;
        #pragma unroll
        for (int i = t; i < 1024; i += 256) Ws4[i] = W4[i];
    }
    {
        float4* Xs4 = (float4*)Xsh;
        #pragma unroll
        for (int i = t; i < 1024; i += 256) {
            int r = i >> 4, k4 = i & 15;
            float4 v = make_float4(0.f, 0.f, 0.f, 0.f);
            if (rowbase + r < n)
                v = ((const float4*)(x + (size_t)(rowbase + r) * DD))[k4];
            Xs4[i] = v;
        }
    }
    __syncthreads();

    int tx = t & 15;
    int ty = t >> 4;

    float acc[4][4];
    #pragma unroll
    for (int i = 0; i < 4; i++)
        #pragma unroll
        for (int j = 0; j < 4; j++) acc[i][j] = 0.f;

    #pragma unroll 8
    for (int k = 0; k < 64; k++) {
        float4 w = ((const float4*)(Wsh + k * DD))[tx];
        float a0 = Xsh[(ty * 4 + 0) * DD + k];
        float a1 = Xsh[(ty * 4 + 1) * DD + k];
        float a2 = Xsh[(ty * 4 + 2) * DD + k];
        float a3 = Xsh[(ty * 4 + 3) * DD + k];
        acc[0][0] += a0 * w.x; acc[0][1] += a0 * w.y; acc[0][2] += a0 * w.z; acc[0][3] += a0 * w.w;
        acc[1][0] += a1 * w.x; acc[1][1] += a1 * w.y; acc[1][2] += a1 * w.z; acc[1][3] += a1 * w.w;
        acc[2][0] += a2 * w.x; acc[2][1] += a2 * w.y; acc[2][2] += a2 * w.z; acc[2][3] += a2 * w.w;
        acc[3][0] += a3 * w.x; acc[3][1] += a3 * w.y; acc[3][2] += a3 * w.z; acc[3][3] += a3 * w.w;
    }

    #pragma unroll
    for (int i = 0; i < 4; i++) {
        int r = rowbase + ty * 4 + i;
        if (r < n) {
            float d = g_dis[r];
            float4 o = make_float4(acc[i][0] * d, acc[i][1] * d, acc[i][2] * d, acc[i][3] * d);
            ((float4*)(g_g + (size_t)r * DD))[tx] = o;
        }
    }
}

// THIN WARPS: 2 warps per node, one float (feature) per lane.
//   agg[v] = dis[v] * (sum_{u->v} g[u] + g[v]) + b, then LayerNorm -> out.
// Cross-warp LN combine via smem (one __syncthreads per block).
// All warps reach the barrier: tail nodes are clamped, stores guarded.
__global__ __launch_bounds__(256) void k_agg_ln(const float* __restrict__ b,
                                                const float* __restrict__ gamma,
                                                const float* __restrict__ beta,
                                                float* __restrict__ out, int n) {
    __shared__ float s_sum[8];
    __shared__ float s_sqs[8];

    int wib   = threadIdx.x >> 5;                       // warp in block: 0..7
    int gw    = blockIdx.x * 8 + wib;                   // global warp
    int node  = gw >> 1;
    int half  = gw & 1;
    int lane  = threadIdx.x & 31;
    int f     = half * 32 + lane;                       // feature 0..63

    int v   = min(node, n - 1);                         // clamp tail, store guarded
    bool ok = (node < n);

    // Params early (independent streams)
    float bf = b[f];
    float gf = gamma[f];
    float tf = beta[f];
    float dv = g_dis[v];

    int rp0 = g_rowptr[v];
    int rp1 = g_rowptr[v + 1];

    float acc = g_g[(size_t)v * DD + f];                // self-loop g[v]

    for (int base = rp0; base < rp1; base += 32) {
        int j = base + lane;
        int c = (j < rp1) ? g_col[j] : NN;              // pad -> permanent zero row
        int nblk = (min(32, rp1 - base) + 7) >> 3;      // warp-uniform 1..4
        for (int bk = 0; bk < nblk; bk++) {
            int s8 = bk * 8;
            int u0 = __shfl_sync(0xffffffffu, c, s8 + 0);
            int u1 = __shfl_sync(0xffffffffu, c, s8 + 1);
            int u2 = __shfl_sync(0xffffffffu, c, s8 + 2);
            int u3 = __shfl_sync(0xffffffffu, c, s8 + 3);
            int u4 = __shfl_sync(0xffffffffu, c, s8 + 4);
            int u5 = __shfl_sync(0xffffffffu, c, s8 + 5);
            int u6 = __shfl_sync(0xffffffffu, c, s8 + 6);
            int u7 = __shfl_sync(0xffffffffu, c, s8 + 7);
            float m0 = g_g[(size_t)u0 * DD + f];
            float m1 = g_g[(size_t)u1 * DD + f];
            float m2 = g_g[(size_t)u2 * DD + f];
            float m3 = g_g[(size_t)u3 * DD + f];
            float m4 = g_g[(size_t)u4 * DD + f];
            float m5 = g_g[(size_t)u5 * DD + f];
            float m6 = g_g[(size_t)u6 * DD + f];
            float m7 = g_g[(size_t)u7 * DD + f];
            acc += ((m0 + m1) + (m2 + m3)) + ((m4 + m5) + (m6 + m7));
        }
    }

    float a = acc * dv + bf;

    // Warp-local partial sums over 32 features
    float s  = a;
    float ss = a * a;
    #pragma unroll
    for (int o = 16; o > 0; o >>= 1) {
        s  += __shfl_xor_sync(0xffffffffu, s, o);
        ss += __shfl_xor_sync(0xffffffffu, ss, o);
    }
    if (lane == 0) { s_sum[wib] = s; s_sqs[wib] = ss; }
    __syncthreads();

    // Combine with partner warp (wib^1 handles the other 32 features of node)
    float S  = s_sum[wib] + s_sum[wib ^ 1];
    float SS = s_sqs[wib] + s_sqs[wib ^ 1];

    float mu  = S * (1.f / 64.f);
    float var = SS * (1.f / 64.f) - mu * mu;
    float inv = rsqrtf(var + 1e-5f);

    if (ok)
        out[(size_t)node * DD + f] = (a - mu) * inv * gf + tf;
}

// ---------------- launch ----------------

extern "C" void kernel_launch(void* const* d_in, const int* in_sizes, int n_in,
                              void* d_out, int out_size) {
    const float* x     = (const float*)d_in[0];
    const int*   ei    = (const int*)d_in[1];
    const float* W     = (const float*)d_in[2];
    const float* b     = (const float*)d_in[3];
    const float* gamma = (const float*)d_in[4];
    const float* beta  = (const float*)d_in[5];

    int n = in_sizes[0] / DD;      // 100000
    int e = in_sizes[1] / 2;       // 800000
    const int* src = ei;
    const int* dst = ei + e;

    k_hist<<<(e + 255) / 256, 256>>>(dst, e);          // kernel 1
    k_scan<<<1, 1024>>>(n);                            // kernel 2 (re-zeroes deg)
    k_scatter<<<(e + 255) / 256, 256>>>(src, dst, e);  // kernel 3

    int gemm_blocks = (n + 63) / 64;
    int agg_blocks  = (2 * n + 7) / 8;   // 2 warps/node, 8 warps/block

    const int NUM_ROUNDS = 4;
    for (int r = 0; r < NUM_ROUNDS; r++) {
        const float* xin = (r == 0) ? x : (const float*)g_x;
        float* xout = (r == NUM_ROUNDS - 1) ? (float*)d_out : g_x;
        k_gemm<<<gemm_blocks, 256>>>(xin, W, n);                // kernel 4 on r=0
        k_agg_ln<<<agg_blocks, 256>>>(b, gamma, beta, xout, n); // kernel 5 on r=0
    }
}

// round 9
// speedup vs baseline: 3.9896x; 1.0166x over previous
#include <cuda_runtime.h>

#define NN 100000
#define EE 800000
#define DD 64

// Scratch (allocation-free rule: __device__ globals).
// g_g has ONE EXTRA ROW (index NN), never written -> stays zero from static
// init; cp.async gather target for padding slots.
__device__ float g_g[(NN + 1) * DD];
__device__ float g_x[NN * DD];      // ping-pong x between rounds
__device__ int   g_deg[NN];
__device__ int   g_rowptr[NN + 1];
__device__ int   g_cursor[NN];
__device__ int   g_col[EE];
__device__ float g_dis[NN];

// ---------------- CSR build ----------------

__global__ void k_hist(const int* __restrict__ dst, int e) {
    int i = blockIdx.x * blockDim.x + threadIdx.x;
    if (i < e) atomicAdd(&g_deg[dst[i]], 1);
}

// Single-block exclusive scan; dis = rsqrt(deg+1); re-zeroes g_deg so the
// next launch's k_hist starts from zero (static init -> replay-identical).
__global__ void k_scan(int n) {
    __shared__ int part[1024];
    int t = threadIdx.x;
    int C = (n + 1023) / 1024;
    int lo = t * C;
    int hi = min(lo + C, n);
    int s = 0;
    for (int i = lo; i < hi; i++) s += g_deg[i];
    part[t] = s;
    __syncthreads();
    for (int off = 1; off < 1024; off <<= 1) {
        int v = (t >= off) ? part[t - off] : 0;
        __syncthreads();
        part[t] += v;
        __syncthreads();
    }
    int run = (t == 0) ? 0 : part[t - 1];
    for (int i = lo; i < hi; i++) {
        int d = g_deg[i];
        g_deg[i] = 0;
        g_rowptr[i] = run;
        g_cursor[i] = run;
        g_dis[i] = rsqrtf((float)(d + 1));   // +1 self-loop
        run += d;
    }
    if (t == 1023) g_rowptr[n] = run;
}

__global__ void k_scatter(const int* __restrict__ src, const int* __restrict__ dst, int e) {
    int i = blockIdx.x * blockDim.x + threadIdx.x;
    if (i < e) {
        int d = dst[i];
        int pos = atomicAdd(&g_cursor[d], 1);
        g_col[pos] = src[i];
    }
}

// ---------------- per-round kernels ----------------

// g = dis[r] * (x @ W). 64x64 tile per block, 256 threads, 4x4 outputs each.
// (~FFMA floor, 26.5us measured; writes only rows < n, pad row NN stays zero.)
__global__ __launch_bounds__(256) void k_gemm(const float* __restrict__ x,
                                              const float* __restrict__ W, int n) {
    __shared__ float Wsh[DD * DD];
    __shared__ float Xsh[DD * DD];

    int t = threadIdx.x;
    int rowbase = blockIdx.x * 64;

    {
        const float4* W4 = (const float4*)W;
        float4* Ws4 = (float4*)Wsh;
        #pragma unroll
        for (int i = t; i < 1024; i += 256) Ws4[i] = W4[i];
    }
    {
        float4* Xs4 = (float4*)Xsh;
        #pragma unroll
        for (int i = t; i < 1024; i += 256) {
            int r = i >> 4, k4 = i & 15;
            float4 v = make_float4(0.f, 0.f, 0.f, 0.f);
            if (rowbase + r < n)
                v = ((const float4*)(x + (size_t)(rowbase + r) * DD))[k4];
            Xs4[i] = v;
        }
    }
    __syncthreads();

    int tx = t & 15;
    int ty = t >> 4;

    float acc[4][4];
    #pragma unroll
    for (int i = 0; i < 4; i++)
        #pragma unroll
        for (int j = 0; j < 4; j++) acc[i][j] = 0.f;

    #pragma unroll 8
    for (int k = 0; k < 64; k++) {
        float4 w = ((const float4*)(Wsh + k * DD))[tx];
        float a0 = Xsh[(ty * 4 + 0) * DD + k];
        float a1 = Xsh[(ty * 4 + 1) * DD + k];
        float a2 = Xsh[(ty * 4 + 2) * DD + k];
        float a3 = Xsh[(ty * 4 + 3) * DD + k];
        acc[0][0] += a0 * w.x; acc[0][1] += a0 * w.y; acc[0][2] += a0 * w.z; acc[0][3] += a0 * w.w;
        acc[1][0] += a1 * w.x; acc[1][1] += a1 * w.y; acc[1][2] += a1 * w.z; acc[1][3] += a1 * w.w;
        acc[2][0] += a2 * w.x; acc[2][1] += a2 * w.y; acc[2][2] += a2 * w.z; acc[2][3] += a2 * w.w;
        acc[3][0] += a3 * w.x; acc[3][1] += a3 * w.y; acc[3][2] += a3 * w.z; acc[3][3] += a3 * w.w;
    }

    #pragma unroll
    for (int i = 0; i < 4; i++) {
        int r = rowbase + ty * 4 + i;
        if (r < n) {
            float d = g_dis[r];
            float4 o = make_float4(acc[i][0] * d, acc[i][1] * d, acc[i][2] * d, acc[i][3] * d);
            ((float4*)(g_g + (size_t)r * DD))[tx] = o;
        }
    }
}

// Warp per node; neighbor rows gathered via cp.async (LDGSTS) into smem:
// a whole 16-edge chunk (4KB) is in flight per warp before any wait.
//   agg[v] = dis[v] * (sum_{u->v} g[u] + g[v]) + b, then LayerNorm -> out
__global__ __launch_bounds__(256) void k_agg_ln(const float* __restrict__ b,
                                                const float* __restrict__ gamma,
                                                const float* __restrict__ beta,
                                                float* __restrict__ out, int n) {
    // 8 warps x 16 edges x 64 floats = 32KB
    __shared__ float sbuf[8 * 16 * DD];

    int wib  = threadIdx.x >> 5;
    int v    = blockIdx.x * 8 + wib;
    int lane = threadIdx.x & 31;
    if (v >= n) return;

    float* wb = sbuf + wib * (16 * DD);              // this warp's 16-row buffer
    int half   = lane >> 4;                          // 0/1: which edge of a pair
    int lane16 = lane & 15;                          // 16B chunk within a row

    // smem address of this lane's 16B slot within edge-row `e`:
    //   wb + e*64 floats + lane16*4 floats
    unsigned wb_u32;
    {
        unsigned long long gen = (unsigned long long)__cvta_generic_to_shared(wb);
        wb_u32 = (unsigned)gen;
    }

    const float2* g2 = (const float2*)g_g;
    float dv = g_dis[v];
    int rp0 = g_rowptr[v];
    int rp1 = g_rowptr[v + 1];

    float2 acc = g2[(size_t)v * 32 + lane];          // self-loop g[v]

    for (int base = rp0; base < rp1; base += 16) {
        int cnt = min(16, rp1 - base);               // warp-uniform 1..16
        int j = base + lane;
        int c = (j < rp1 && lane < 16) ? g_col[j] : NN;   // lanes 0-15 hold indices

        // Issue cp.async: pair of edges per instruction (lanes 0-15 edge ee,
        // lanes 16-31 edge ee+1). Odd tail loads pad row NN (zero).
        for (int ee = 0; ee < cnt; ee += 2) {
            int u = __shfl_sync(0xffffffffu, c, ee + half);   // src lane <= 15
            const float* gptr = g_g + (size_t)u * DD + lane16 * 4;
            unsigned saddr = wb_u32 + (unsigned)((ee + half) * DD + lane16 * 4) * 4u;
            asm volatile("cp.async.cg.shared.global [%0], [%1], 16;\n"
                         :: "r"(saddr), "l"(gptr));
        }
        asm volatile("cp.async.commit_group;\n");
        asm volatile("cp.async.wait_group 0;\n");
        __syncwarp();

        // Accumulate: conflict-free LDS.64 per lane per edge.
        int cnt2 = (cnt + 1) & ~1;                   // includes zero pad if odd
        const float2* wb2 = (const float2*)wb;
        for (int ee = 0; ee < cnt2; ee++) {
            float2 m = wb2[ee * 32 + lane];
            acc.x += m.x;
            acc.y += m.y;
        }
        __syncwarp();
    }

    float2 bb = ((const float2*)b)[lane];
    float a0 = acc.x * dv + bb.x;
    float a1 = acc.y * dv + bb.y;

    // LayerNorm over 64 features (2 per lane, full-warp reduction)
    float s  = a0 + a1;
    float ss = a0 * a0 + a1 * a1;
    #pragma unroll
    for (int o = 16; o > 0; o >>= 1) {
        s  += __shfl_xor_sync(0xffffffffu, s, o);
        ss += __shfl_xor_sync(0xffffffffu, ss, o);
    }
    float mu  = s * (1.f / 64.f);
    float var = ss * (1.f / 64.f) - mu * mu;
    float inv = rsqrtf(var + 1e-5f);

    float2 gm = ((const float2*)gamma)[lane];
    float2 bt = ((const float2*)beta)[lane];
    float2 o2;
    o2.x = (a0 - mu) * inv * gm.x + bt.x;
    o2.y = (a1 - mu) * inv * gm.y + bt.y;
    ((float2*)out)[(size_t)v * 32 + lane] = o2;
}

// ---------------- launch ----------------

extern "C" void kernel_launch(void* const* d_in, const int* in_sizes, int n_in,
                              void* d_out, int out_size) {
    const float* x     = (const float*)d_in[0];
    const int*   ei    = (const int*)d_in[1];
    const float* W     = (const float*)d_in[2];
    const float* b     = (const float*)d_in[3];
    const float* gamma = (const float*)d_in[4];
    const float* beta  = (const float*)d_in[5];

    int n = in_sizes[0] / DD;      // 100000
    int e = in_sizes[1] / 2;       // 800000
    const int* src = ei;
    const int* dst = ei + e;

    k_hist<<<(e + 255) / 256, 256>>>(dst, e);          // kernel 1
    k_scan<<<1, 1024>>>(n);                            // kernel 2 (re-zeroes deg)
    k_scatter<<<(e + 255) / 256, 256>>>(src, dst, e);  // kernel 3

    int gemm_blocks = (n + 63) / 64;
    int agg_blocks  = (n + 7) / 8;   // warp per node, 8 warps/block

    const int NUM_ROUNDS = 4;
    for (int r = 0; r < NUM_ROUNDS; r++) {
        const float* xin = (r == 0) ? x : (const float*)g_x;
        float* xout = (r == NUM_ROUNDS - 1) ? (float*)d_out : g_x;
        k_gemm<<<gemm_blocks, 256>>>(xin, W, n);                // kernel 4 on r=0
        k_agg_ln<<<agg_blocks, 256>>>(b, gamma, beta, xout, n); // kernel 5 on r=0
    }
}

// round 10
// speedup vs baseline: 3.9992x; 1.0024x over previous
#include <cuda_runtime.h>

#define NN 100000
#define EE 800000
#define DD 64

#define SCATTER_BLOCKS 3125   // ceil(EE/256)
#define GEMM_BLOCKS    1563   // ceil(NN/64)

// Scratch (allocation-free rule: __device__ globals)
__device__ float g_g[NN * DD];      // g = dis * (x @ W)
__device__ float g_x[NN * DD];      // ping-pong x between rounds
__device__ int   g_deg[NN];
__device__ int   g_rowptr[NN + 1];
__device__ int   g_cursor[NN];
__device__ int   g_col[EE];
__device__ float g_dis[NN];

// ---------------- CSR build ----------------

__global__ void k_hist(const int* __restrict__ dst, int e) {
    int i = blockIdx.x * blockDim.x + threadIdx.x;
    if (i < e) atomicAdd(&g_deg[dst[i]], 1);
}

// Single-block exclusive scan; dis = rsqrt(deg+1); re-zeroes g_deg so the
// next launch's k_hist starts from zero (static init -> replay-identical).
__global__ void k_scan(int n) {
    __shared__ int part[1024];
    int t = threadIdx.x;
    int C = (n + 1023) / 1024;
    int lo = t * C;
    int hi = min(lo + C, n);
    int s = 0;
    for (int i = lo; i < hi; i++) s += g_deg[i];
    part[t] = s;
    __syncthreads();
    for (int off = 1; off < 1024; off <<= 1) {
        int v = (t >= off) ? part[t - off] : 0;
        __syncthreads();
        part[t] += v;
        __syncthreads();
    }
    int run = (t == 0) ? 0 : part[t - 1];
    for (int i = lo; i < hi; i++) {
        int d = g_deg[i];
        g_deg[i] = 0;
        g_rowptr[i] = run;
        g_cursor[i] = run;
        g_dis[i] = rsqrtf((float)(d + 1));   // +1 self-loop
        run += d;
    }
    if (t == 1023) g_rowptr[n] = run;
}

// ---------------- GEMM core (shared by fused + standalone kernels) ----------------

__device__ __forceinline__ void gemm_tile(const float* __restrict__ x,
                                          const float* __restrict__ W,
                                          int rowbase, int n,
                                          float* Wsh, float* Xsh, int t) {
    {
        const float4* W4 = (const float4*)W;
        float4* Ws4 = (float4*)Wsh;
        #pragma unroll
        for (int i = t; i < 1024; i += 256) Ws4[i] = W4[i];
    }
    {
        float4* Xs4 = (float4*)Xsh;
        #pragma unroll
        for (int i = t; i < 1024; i += 256) {
            int r = i >> 4, k4 = i & 15;
            float4 v = make_float4(0.f, 0.f, 0.f, 0.f);
            if (rowbase + r < n)
                v = ((const float4*)(x + (size_t)(rowbase + r) * DD))[k4];
            Xs4[i] = v;
        }
    }
    __syncthreads();

    int tx = t & 15;
    int ty = t >> 4;

    float acc[4][4];
    #pragma unroll
    for (int i = 0; i < 4; i++)
        #pragma unroll
        for (int j = 0; j < 4; j++) acc[i][j] = 0.f;

    #pragma unroll 8
    for (int k = 0; k < 64; k++) {
        float4 w = ((const float4*)(Wsh + k * DD))[tx];
        float a0 = Xsh[(ty * 4 + 0) * DD + k];
        float a1 = Xsh[(ty * 4 + 1) * DD + k];
        float a2 = Xsh[(ty * 4 + 2) * DD + k];
        float a3 = Xsh[(ty * 4 + 3) * DD + k];
        acc[0][0] += a0 * w.x; acc[0][1] += a0 * w.y; acc[0][2] += a0 * w.z; acc[0][3] += a0 * w.w;
        acc[1][0] += a1 * w.x; acc[1][1] += a1 * w.y; acc[1][2] += a1 * w.z; acc[1][3] += a1 * w.w;
        acc[2][0] += a2 * w.x; acc[2][1] += a2 * w.y; acc[2][2] += a2 * w.z; acc[2][3] += a2 * w.w;
        acc[3][0] += a3 * w.x; acc[3][1] += a3 * w.y; acc[3][2] += a3 * w.z; acc[3][3] += a3 * w.w;
    }

    #pragma unroll
    for (int i = 0; i < 4; i++) {
        int r = rowbase + ty * 4 + i;
        if (r < n) {
            float d = g_dis[r];
            float4 o = make_float4(acc[i][0] * d, acc[i][1] * d, acc[i][2] * d, acc[i][3] * d);
            ((float4*)(g_g + (size_t)r * DD))[tx] = o;
        }
    }
}

// Fused: blocks [0, SCATTER_BLOCKS) do CSR scatter; the rest do round-0 GEMM.
// Independent outputs (g_col vs g_g); both depend only on k_scan.
__global__ __launch_bounds__(256) void k_scatter_gemm(const int* __restrict__ src,
                                                      const int* __restrict__ dst, int e,
                                                      const float* __restrict__ x,
                                                      const float* __restrict__ W, int n) {
    __shared__ float Wsh[DD * DD];
    __shared__ float Xsh[DD * DD];

    if (blockIdx.x < SCATTER_BLOCKS) {
        int i = blockIdx.x * 256 + threadIdx.x;
        if (i < e) {
            int d = dst[i];
            int pos = atomicAdd(&g_cursor[d], 1);
            g_col[pos] = src[i];
        }
        return;
    }
    int rowbase = (blockIdx.x - SCATTER_BLOCKS) * 64;
    gemm_tile(x, W, rowbase, n, Wsh, Xsh, threadIdx.x);
}

// Standalone GEMM for rounds 1..3
__global__ __launch_bounds__(256) void k_gemm(const float* __restrict__ x,
                                              const float* __restrict__ W, int n) {
    __shared__ float Wsh[DD * DD];
    __shared__ float Xsh[DD * DD];
    gemm_tile(x, W, blockIdx.x * 64, n, Wsh, Xsh, threadIdx.x);
}

// Warp per node (R2-measured loop shape):
//   agg[v] = dis[v] * (sum_{u->v} g[u] + g[v]) + b, then LayerNorm -> out
__global__ __launch_bounds__(256) void k_agg_ln(const float* __restrict__ b,
                                                const float* __restrict__ gamma,
                                                const float* __restrict__ beta,
                                                float* __restrict__ out, int n) {
    int v    = (blockIdx.x * blockDim.x + threadIdx.x) >> 5;
    int lane = threadIdx.x & 31;
    if (v >= n) return;

    const float2* g2 = (const float2*)g_g;
    float dv = g_dis[v];
    float2 acc = g2[(size_t)v * 32 + lane];   // self-loop g[v]

    int rp0 = g_rowptr[v];
    int rp1 = g_rowptr[v + 1];
    for (int base = rp0; base < rp1; base += 32) {
        int j = base + lane;
        int c = (j < rp1) ? g_col[j] : 0;
        int cnt = min(32, rp1 - base);
        int jj = 0;
        for (; jj + 4 <= cnt; jj += 4) {
            int u0 = __shfl_sync(0xffffffffu, c, jj + 0);
            int u1 = __shfl_sync(0xffffffffu, c, jj + 1);
            int u2 = __shfl_sync(0xffffffffu, c, jj + 2);
            int u3 = __shfl_sync(0xffffffffu, c, jj + 3);
            float2 m0 = g2[(size_t)u0 * 32 + lane];
            float2 m1 = g2[(size_t)u1 * 32 + lane];
            float2 m2 = g2[(size_t)u2 * 32 + lane];
            float2 m3 = g2[(size_t)u3 * 32 + lane];
            acc.x += (m0.x + m1.x) + (m2.x + m3.x);
            acc.y += (m0.y + m1.y) + (m2.y + m3.y);
        }
        for (; jj < cnt; jj++) {
            int u = __shfl_sync(0xffffffffu, c, jj);
            float2 m = g2[(size_t)u * 32 + lane];
            acc.x += m.x;
            acc.y += m.y;
        }
    }

    float2 bb = ((const float2*)b)[lane];
    float a0 = acc.x * dv + bb.x;
    float a1 = acc.y * dv + bb.y;

    // LayerNorm over 64 features (2 per lane)
    float s  = a0 + a1;
    float ss = a0 * a0 + a1 * a1;
    #pragma unroll
    for (int o = 16; o > 0; o >>= 1) {
        s  += __shfl_xor_sync(0xffffffffu, s, o);
        ss += __shfl_xor_sync(0xffffffffu, ss, o);
    }
    float mu  = s * (1.f / 64.f);
    float var = ss * (1.f / 64.f) - mu * mu;
    float inv = rsqrtf(var + 1e-5f);

    float2 gm = ((const float2*)gamma)[lane];
    float2 bt = ((const float2*)beta)[lane];
    float2 o2;
    o2.x = (a0 - mu) * inv * gm.x + bt.x;
    o2.y = (a1 - mu) * inv * gm.y + bt.y;
    ((float2*)out)[(size_t)v * 32 + lane] = o2;
}

// ---------------- launch ----------------

extern "C" void kernel_launch(void* const* d_in, const int* in_sizes, int n_in,
                              void* d_out, int out_size) {
    const float* x     = (const float*)d_in[0];
    const int*   ei    = (const int*)d_in[1];
    const float* W     = (const float*)d_in[2];
    const float* b     = (const float*)d_in[3];
    const float* gamma = (const float*)d_in[4];
    const float* beta  = (const float*)d_in[5];

    int n = in_sizes[0] / DD;      // 100000
    int e = in_sizes[1] / 2;       // 800000
    const int* src = ei;
    const int* dst = ei + e;

    k_hist<<<(e + 255) / 256, 256>>>(dst, e);                       // kernel 1
    k_scan<<<1, 1024>>>(n);                                         // kernel 2
    k_scatter_gemm<<<SCATTER_BLOCKS + GEMM_BLOCKS, 256>>>(          // kernel 3
        src, dst, e, x, W, n);

    int agg_blocks = (n + 7) / 8;   // warp per node, 8 warps/block

    const int NUM_ROUNDS = 4;
    for (int r = 0; r < NUM_ROUNDS; r++) {
        if (r > 0)
            k_gemm<<<GEMM_BLOCKS, 256>>>((const float*)g_x, W, n);
        float* xout = (r == NUM_ROUNDS - 1) ? (float*)d_out : g_x;
        k_agg_ln<<<agg_blocks, 256>>>(b, gamma, beta, xout, n);     // kernel 4 on r=0 -> PROFILED
    }
}